// round 9
// baseline (speedup 1.0000x reference)
#include <cuda_runtime.h>
#include <cstdint>

#define N_ATOMS 50000
#define N_PAIRS 600000
#define DB 128
#define NRBF 20

#define TILE_P 128
#define N_TILES ((N_PAIRS + TILE_P - 1) / TILE_P)   // 4688
#define EDGE_GRID 296

#define A_ELEMS (128 * 64)        // 32 KB
#define B_ELEMS (64 * 136)        // 34.8 KB
#define SMEM_EDGE ((A_ELEMS + B_ELEMS) * 4)

// Scratch (allocation-free rule: __device__ globals)
__device__ float g_h[(size_t)N_ATOMS * DB];    // 25.6 MB
__device__ float g_agg[(size_t)N_ATOMS * DB];  // 25.6 MB
__device__ int2  g_pairs[N_PAIRS];             // 4.8 MB

// Fast shifted-softplus: softplus(x) - ln2, overflow-safe, MUFU-based.
__device__ __forceinline__ float ssp(float x) {
    float t = __expf(-fabsf(x));
    return fmaxf(x, 0.f) + __logf(1.f + t) - 0.6931471805599453f;
}

__device__ __forceinline__ void red_add_v2(float* a, float2 v) {
    asm volatile("red.global.add.v2.f32 [%0], {%1,%2};"
                 :: "l"(a), "f"(v.x), "f"(v.y)
                 : "memory");
}

// tf32 round-to-nearest: destination of cvt.rna.tf32.f32 is a b32 register.
__device__ __forceinline__ float tf32_rna(float x) {
    uint32_t y;
    asm("cvt.rna.tf32.f32 %0, %1;" : "=r"(y) : "f"(x));
    return __uint_as_float(y);
}

// Warp-level tf32 MMA: D[16,8] += A[16,8] * B[8,8]  (fp32 accumulate)
__device__ __forceinline__ void mma_tf32(float* d,
                                         uint32_t a0, uint32_t a1,
                                         uint32_t a2, uint32_t a3,
                                         uint32_t b0, uint32_t b1) {
    asm volatile(
        "mma.sync.aligned.m16n8k8.row.col.f32.tf32.tf32.f32 "
        "{%0,%1,%2,%3}, {%4,%5,%6,%7}, {%8,%9}, {%0,%1,%2,%3};"
        : "+f"(d[0]), "+f"(d[1]), "+f"(d[2]), "+f"(d[3])
        : "r"(a0), "r"(a1), "r"(a2), "r"(a3), "r"(b0), "r"(b1));
}

// A-tile smem index: row-major [128][64] with XOR swizzle so the mma
// A-fragment loads hit 32 distinct banks.
__device__ __forceinline__ int a_idx(int r, int c) {
    return r * 64 + (c ^ ((r & 7) << 2));
}

// ----------------------------------------------------------------------------
// Pairlist convert to int2 with per-block dtype detection (int64 vs int32).
// ----------------------------------------------------------------------------
__global__ void convert_idx_kernel(const void* __restrict__ pl) {
    __shared__ unsigned int s_or;
    if (threadIdx.x == 0) s_or = 0u;
    __syncthreads();
    const unsigned int* pw = (const unsigned int*)pl;
    unsigned int v = 0u;
    for (int i = threadIdx.x; i < 1024; i += blockDim.x)
        v |= pw[2 * i + 1];
    atomicOr(&s_or, v);
    __syncthreads();
    const bool is64 = (s_or == 0u);

    int p = blockIdx.x * blockDim.x + threadIdx.x;
    if (p >= N_PAIRS) return;
    int i, j;
    if (is64) {
        const long long* q = (const long long*)pl;
        i = (int)q[p];
        j = (int)q[N_PAIRS + p];
    } else {
        const int* q = (const int*)pl;
        i = q[p];
        j = q[N_PAIRS + p];
    }
    g_pairs[p] = make_int2(i, j);
}

__global__ void zero_agg_kernel() {
    size_t idx = (size_t)blockIdx.x * blockDim.x + threadIdx.x;
    size_t n4 = (size_t)N_ATOMS * DB / 4;
    if (idx < n4)
        ((float4*)g_agg)[idx] = make_float4(0.f, 0.f, 0.f, 0.f);
}

// ----------------------------------------------------------------------------
// C[M,128] = A[M,128] @ W[128,128] + bias  (optional ssp epilogue) — fp32 SGEMM
// ----------------------------------------------------------------------------
template <bool DO_SSP>
__global__ __launch_bounds__(256) void gemm128_kernel(
    const float* __restrict__ A, const float* __restrict__ W,
    const float* __restrict__ bias, float* __restrict__ C, int M)
{
    __shared__ float As[16 * 132];
    __shared__ float Bs[16 * 128];

    const int tid = threadIdx.x;
    const int tx = tid & 15;
    const int ty = tid >> 4;
    const int m0 = blockIdx.x * 128;

    float acc[8][8];
    #pragma unroll
    for (int i = 0; i < 8; i++)
        #pragma unroll
        for (int j = 0; j < 8; j++) acc[i][j] = 0.f;

    for (int kt = 0; kt < 128; kt += 16) {
        #pragma unroll
        for (int i = 0; i < 2; i++) {
            int idx = tid * 2 + i;
            int row = idx >> 2;
            int c4  = idx & 3;
            float4 av = make_float4(0.f, 0.f, 0.f, 0.f);
            int grow = m0 + row;
            if (grow < M)
                av = *(const float4*)&A[(size_t)grow * DB + kt + c4 * 4];
            As[(c4 * 4 + 0) * 132 + row] = av.x;
            As[(c4 * 4 + 1) * 132 + row] = av.y;
            As[(c4 * 4 + 2) * 132 + row] = av.z;
            As[(c4 * 4 + 3) * 132 + row] = av.w;

            int k = idx >> 5;
            int c = idx & 31;
            *(float4*)&Bs[k * 128 + c * 4] =
                *(const float4*)&W[(size_t)(kt + k) * DB + c * 4];
        }
        __syncthreads();

        #pragma unroll
        for (int kk = 0; kk < 16; kk++) {
            float a[8], b[8];
            *(float4*)&a[0] = *(const float4*)&As[kk * 132 + ty * 8];
            *(float4*)&a[4] = *(const float4*)&As[kk * 132 + ty * 8 + 4];
            *(float4*)&b[0] = *(const float4*)&Bs[kk * 128 + tx * 8];
            *(float4*)&b[4] = *(const float4*)&Bs[kk * 128 + tx * 8 + 4];
            #pragma unroll
            for (int i = 0; i < 8; i++)
                #pragma unroll
                for (int j = 0; j < 8; j++)
                    acc[i][j] = fmaf(a[i], b[j], acc[i][j]);
        }
        __syncthreads();
    }

    float bb[8];
    *(float4*)&bb[0] = *(const float4*)&bias[tx * 8];
    *(float4*)&bb[4] = *(const float4*)&bias[tx * 8 + 4];

    #pragma unroll
    for (int i = 0; i < 8; i++) {
        int grow = m0 + ty * 8 + i;
        if (grow >= M) continue;
        float v[8];
        #pragma unroll
        for (int j = 0; j < 8; j++) {
            float c = acc[i][j] + bb[j];
            v[j] = DO_SSP ? ssp(c) : c;
        }
        *(float4*)&C[(size_t)grow * DB + tx * 8]     = *(float4*)&v[0];
        *(float4*)&C[(size_t)grow * DB + tx * 8 + 4] = *(float4*)&v[4];
    }
}

// ----------------------------------------------------------------------------
// Edge kernel v3: Wij via warp-level split-tf32 mma.sync (exact to ~1e-7):
//   A' cols: [0..19]=f_hi [20..39]=f_hi [40..59]=f_lo [60..61]=1 [62..63]=0
//   B' rows: [0..19]=w_hi [20..39]=w_lo [40..59]=w_hi [60]=b_hi [61]=b_lo
//   D = f_hi*w + f_lo*w_hi + b  ==  f@Wf + b  (+O(2^-22))
// Persistent blocks (296), 8 warps; warp w owns output cols [16w, 16w+16).
// D stays in registers; epilogue: ssp, *rcut, gather h[j], red agg[i].
// Dynamic smem: As[128*64] then Bs[64*136].
// ----------------------------------------------------------------------------
__global__ void __launch_bounds__(256, 2) edge_mma_kernel(
    const float* __restrict__ f, const float* __restrict__ rcut,
    const float* __restrict__ Wf, const float* __restrict__ bf)
{
    extern __shared__ float smem_dyn[];
    float* const As = smem_dyn;             // 128*64
    float* const Bs = smem_dyn + A_ELEMS;   // 64*136

    const int tid = threadIdx.x;
    const int wid = tid >> 5;        // 0..7
    const int lane = tid & 31;
    const int lq = lane >> 2;        // groupID 0..7
    const int la = lane & 3;         // threadID_in_group 0..3
    const int cb = wid * 16;         // output col base for this warp

    // ---- Stage B' (once per block) ----
    for (int e = tid; e < 64 * 128; e += 256) {
        int k = e >> 7;
        int n = e & 127;
        float val;
        if (k < 20) {
            val = tf32_rna(Wf[k * DB + n]);
        } else if (k < 40) {
            float w = Wf[(k - 20) * DB + n];
            val = tf32_rna(w - tf32_rna(w));
        } else if (k < 60) {
            val = tf32_rna(Wf[(k - 40) * DB + n]);
        } else if (k == 60) {
            val = tf32_rna(bf[n]);
        } else if (k == 61) {
            float b = bf[n];
            val = tf32_rna(b - tf32_rna(b));
        } else {
            val = 0.f;
        }
        Bs[k * 136 + n] = val;
    }
    // ---- Constant A' cols (ones for bias, zeros for padding) ----
    for (int r = tid; r < 128; r += 256) {
        As[a_idx(r, 60)] = 1.f;
        As[a_idx(r, 61)] = 1.f;
        As[a_idx(r, 62)] = 0.f;
        As[a_idx(r, 63)] = 0.f;
    }

    for (int tile = blockIdx.x; tile < N_TILES; tile += EDGE_GRID) {
        __syncthreads();   // previous iteration's A reads done (also covers B staging)

        // ---- Stage A' (f tile split hi/lo). Thread t: row t>>1, 10 cols. ----
        {
            int r = tid >> 1;
            int p = tile * TILE_P + r;
            int c0 = (tid & 1) * 10;
            #pragma unroll
            for (int i = 0; i < 10; i++) {
                int k = c0 + i;
                float x = (p < N_PAIRS) ? __ldg(&f[(size_t)p * NRBF + k]) : 0.f;
                float hi = tf32_rna(x);
                float lo = tf32_rna(x - hi);
                As[a_idx(r, k)]      = hi;
                As[a_idx(r, k + 20)] = hi;
                As[a_idx(r, k + 40)] = lo;
            }
        }
        __syncthreads();

        // ---- MMA: D[128 pairs, 16 cols] for this warp ----
        float acc[8][2][4];
        #pragma unroll
        for (int mt = 0; mt < 8; mt++)
            #pragma unroll
            for (int nt = 0; nt < 2; nt++)
                #pragma unroll
                for (int q = 0; q < 4; q++) acc[mt][nt][q] = 0.f;

        #pragma unroll
        for (int kt = 0; kt < 8; kt++) {
            const int krow = kt * 8 + la;
            const uint32_t b00 = __float_as_uint(Bs[krow * 136 + cb + lq]);
            const uint32_t b01 = __float_as_uint(Bs[(krow + 4) * 136 + cb + lq]);
            const uint32_t b10 = __float_as_uint(Bs[krow * 136 + cb + 8 + lq]);
            const uint32_t b11 = __float_as_uint(Bs[(krow + 4) * 136 + cb + 8 + lq]);
            const int cx = (kt * 8 + la) ^ (lq << 2);
            #pragma unroll
            for (int mt = 0; mt < 8; mt++) {
                const int row = mt * 16 + lq;
                uint32_t a0 = __float_as_uint(As[row * 64 + cx]);
                uint32_t a1 = __float_as_uint(As[(row + 8) * 64 + cx]);
                uint32_t a2 = __float_as_uint(As[row * 64 + (cx ^ 4)]);
                uint32_t a3 = __float_as_uint(As[(row + 8) * 64 + (cx ^ 4)]);
                mma_tf32(acc[mt][0], a0, a1, a2, a3, b00, b01);
                mma_tf32(acc[mt][1], a0, a1, a2, a3, b10, b11);
            }
        }

        // ---- Epilogue: D regs -> ssp -> *rcut -> gather h -> red agg ----
        #pragma unroll
        for (int mt = 0; mt < 8; mt++) {
            #pragma unroll
            for (int half = 0; half < 2; half++) {
                const int p = tile * TILE_P + mt * 16 + half * 8 + lq;
                if (p < N_PAIRS) {
                    int2 ij = g_pairs[p];
                    float rc = __ldg(&rcut[p]);
                    const float* hrow = &g_h[(size_t)ij.y * DB + cb + 2 * la];
                    float* arow = &g_agg[(size_t)ij.x * DB + cb + 2 * la];
                    #pragma unroll
                    for (int nt = 0; nt < 2; nt++) {
                        float d0 = acc[mt][nt][half * 2 + 0];
                        float d1 = acc[mt][nt][half * 2 + 1];
                        float w0 = ssp(d0) * rc;
                        float w1 = ssp(d1) * rc;
                        float2 hv = *(const float2*)(hrow + nt * 8);
                        red_add_v2(arow + nt * 8, make_float2(hv.x * w0, hv.y * w1));
                    }
                }
            }
        }
    }
}

// ----------------------------------------------------------------------------

extern "C" void kernel_launch(void* const* d_in, const int* in_sizes, int n_in,
                              void* d_out, int out_size)
{
    const float* x     = (const float*)d_in[0];
    const void*  pl    = d_in[1];
    const float* f_ij  = (const float*)d_in[2];
    const float* rcut  = (const float*)d_in[3];
    const float* W_in  = (const float*)d_in[4];
    const float* b_in  = (const float*)d_in[5];
    const float* W_f   = (const float*)d_in[6];
    const float* b_f   = (const float*)d_in[7];
    const float* W_out = (const float*)d_in[8];
    const float* b_out = (const float*)d_in[9];
    float*       out   = (float*)d_out;

    float* hbuf;  cudaGetSymbolAddress((void**)&hbuf, g_h);
    float* abuf;  cudaGetSymbolAddress((void**)&abuf, g_agg);

    // Opt-in to >48KB dynamic smem (idempotent, capture-safe host call).
    cudaFuncSetAttribute(edge_mma_kernel,
                         cudaFuncAttributeMaxDynamicSharedMemorySize, SMEM_EDGE);

    const int gemm_grid = (N_ATOMS + 127) / 128;  // 391

    // 0) pairlist convert (with in-kernel dtype sniff)
    convert_idx_kernel<<<(N_PAIRS + 255) / 256, 256>>>(pl);
    // 1) agg = 0
    zero_agg_kernel<<<(N_ATOMS * DB / 4 + 255) / 256, 256>>>();
    // 2) h = x @ W_in + b_in
    gemm128_kernel<false><<<gemm_grid, 256>>>(x, W_in, b_in, hbuf, N_ATOMS);
    // 3) edges: warp-MMA Wij + gather/modulate/scatter
    edge_mma_kernel<<<EDGE_GRID, 256, SMEM_EDGE>>>(f_ij, rcut, W_f, b_f);
    // 4) out = ssp(agg @ W_out + b_out)
    gemm128_kernel<true><<<gemm_grid, 256>>>(abuf, W_out, b_out, out, N_ATOMS);
}

// round 10
// speedup vs baseline: 1.2111x; 1.2111x over previous
#include <cuda_runtime.h>
#include <cstdint>

#define N_ATOMS 50000
#define N_PAIRS 600000
#define DB 128
#define NRBF 20

#define TILE_P 128
#define N_TILES ((N_PAIRS + TILE_P - 1) / TILE_P)   // 4688
#define EDGE_GRID 296

// Dynamic smem layout (floats):
//   [0 .. 128*136)          Wij tile, rows=pairs, stride 136  (69.6 KB)
//       (first 128*64 words double as the A'-staging region before MMA)
//   [128*136 .. +64*136)    B' tile, stride 136               (34.8 KB)
#define W_ELEMS (128 * 136)
#define B_ELEMS (64 * 136)
#define SMEM_EDGE ((W_ELEMS + B_ELEMS) * 4)   // 104448 B -> 2 blocks/SM

// Scratch (allocation-free rule: __device__ globals)
__device__ float g_h[(size_t)N_ATOMS * DB];    // 25.6 MB
__device__ float g_agg[(size_t)N_ATOMS * DB];  // 25.6 MB
__device__ int2  g_pairs[N_PAIRS];             // 4.8 MB

// Fast shifted-softplus: softplus(x) - ln2, overflow-safe, MUFU-based.
__device__ __forceinline__ float ssp(float x) {
    float t = __expf(-fabsf(x));
    return fmaxf(x, 0.f) + __logf(1.f + t) - 0.6931471805599453f;
}

__device__ __forceinline__ void red_add_v4(float* a, float4 v) {
    asm volatile("red.global.add.v4.f32 [%0], {%1,%2,%3,%4};"
                 :: "l"(a), "f"(v.x), "f"(v.y), "f"(v.z), "f"(v.w)
                 : "memory");
}

// tf32 round-to-nearest: destination of cvt.rna.tf32.f32 is a b32 register.
__device__ __forceinline__ float tf32_rna(float x) {
    uint32_t y;
    asm("cvt.rna.tf32.f32 %0, %1;" : "=r"(y) : "f"(x));
    return __uint_as_float(y);
}

// Warp-level tf32 MMA: D[16,8] += A[16,8] * B[8,8]  (fp32 accumulate)
__device__ __forceinline__ void mma_tf32(float* d,
                                         uint32_t a0, uint32_t a1,
                                         uint32_t a2, uint32_t a3,
                                         uint32_t b0, uint32_t b1) {
    asm volatile(
        "mma.sync.aligned.m16n8k8.row.col.f32.tf32.tf32.f32 "
        "{%0,%1,%2,%3}, {%4,%5,%6,%7}, {%8,%9}, {%0,%1,%2,%3};"
        : "+f"(d[0]), "+f"(d[1]), "+f"(d[2]), "+f"(d[3])
        : "r"(a0), "r"(a1), "r"(a2), "r"(a3), "r"(b0), "r"(b1));
}

// A'-staging index: row-major [128][64] with XOR swizzle -> conflict-free
// mma A-fragment loads. (Same mapping as R9, validated by rel_err 8e-7.)
__device__ __forceinline__ int a_idx(int r, int c) {
    return r * 64 + (c ^ ((r & 7) << 2));
}

// ----------------------------------------------------------------------------
// Pairlist convert to int2 with per-block dtype detection (int64 vs int32).
// ----------------------------------------------------------------------------
__global__ void convert_idx_kernel(const void* __restrict__ pl) {
    __shared__ unsigned int s_or;
    if (threadIdx.x == 0) s_or = 0u;
    __syncthreads();
    const unsigned int* pw = (const unsigned int*)pl;
    unsigned int v = 0u;
    for (int i = threadIdx.x; i < 1024; i += blockDim.x)
        v |= pw[2 * i + 1];
    atomicOr(&s_or, v);
    __syncthreads();
    const bool is64 = (s_or == 0u);

    int p = blockIdx.x * blockDim.x + threadIdx.x;
    if (p >= N_PAIRS) return;
    int i, j;
    if (is64) {
        const long long* q = (const long long*)pl;
        i = (int)q[p];
        j = (int)q[N_PAIRS + p];
    } else {
        const int* q = (const int*)pl;
        i = q[p];
        j = q[N_PAIRS + p];
    }
    g_pairs[p] = make_int2(i, j);
}

__global__ void zero_agg_kernel() {
    size_t idx = (size_t)blockIdx.x * blockDim.x + threadIdx.x;
    size_t n4 = (size_t)N_ATOMS * DB / 4;
    if (idx < n4)
        ((float4*)g_agg)[idx] = make_float4(0.f, 0.f, 0.f, 0.f);
}

// ----------------------------------------------------------------------------
// C[M,128] = A[M,128] @ W[128,128] + bias  (optional ssp epilogue) — fp32 SGEMM
// ----------------------------------------------------------------------------
template <bool DO_SSP>
__global__ __launch_bounds__(256) void gemm128_kernel(
    const float* __restrict__ A, const float* __restrict__ W,
    const float* __restrict__ bias, float* __restrict__ C, int M)
{
    __shared__ float As[16 * 132];
    __shared__ float Bs[16 * 128];

    const int tid = threadIdx.x;
    const int tx = tid & 15;
    const int ty = tid >> 4;
    const int m0 = blockIdx.x * 128;

    float acc[8][8];
    #pragma unroll
    for (int i = 0; i < 8; i++)
        #pragma unroll
        for (int j = 0; j < 8; j++) acc[i][j] = 0.f;

    for (int kt = 0; kt < 128; kt += 16) {
        #pragma unroll
        for (int i = 0; i < 2; i++) {
            int idx = tid * 2 + i;
            int row = idx >> 2;
            int c4  = idx & 3;
            float4 av = make_float4(0.f, 0.f, 0.f, 0.f);
            int grow = m0 + row;
            if (grow < M)
                av = *(const float4*)&A[(size_t)grow * DB + kt + c4 * 4];
            As[(c4 * 4 + 0) * 132 + row] = av.x;
            As[(c4 * 4 + 1) * 132 + row] = av.y;
            As[(c4 * 4 + 2) * 132 + row] = av.z;
            As[(c4 * 4 + 3) * 132 + row] = av.w;

            int k = idx >> 5;
            int c = idx & 31;
            *(float4*)&Bs[k * 128 + c * 4] =
                *(const float4*)&W[(size_t)(kt + k) * DB + c * 4];
        }
        __syncthreads();

        #pragma unroll
        for (int kk = 0; kk < 16; kk++) {
            float a[8], b[8];
            *(float4*)&a[0] = *(const float4*)&As[kk * 132 + ty * 8];
            *(float4*)&a[4] = *(const float4*)&As[kk * 132 + ty * 8 + 4];
            *(float4*)&b[0] = *(const float4*)&Bs[kk * 128 + tx * 8];
            *(float4*)&b[4] = *(const float4*)&Bs[kk * 128 + tx * 8 + 4];
            #pragma unroll
            for (int i = 0; i < 8; i++)
                #pragma unroll
                for (int j = 0; j < 8; j++)
                    acc[i][j] = fmaf(a[i], b[j], acc[i][j]);
        }
        __syncthreads();
    }

    float bb[8];
    *(float4*)&bb[0] = *(const float4*)&bias[tx * 8];
    *(float4*)&bb[4] = *(const float4*)&bias[tx * 8 + 4];

    #pragma unroll
    for (int i = 0; i < 8; i++) {
        int grow = m0 + ty * 8 + i;
        if (grow >= M) continue;
        float v[8];
        #pragma unroll
        for (int j = 0; j < 8; j++) {
            float c = acc[i][j] + bb[j];
            v[j] = DO_SSP ? ssp(c) : c;
        }
        *(float4*)&C[(size_t)grow * DB + tx * 8]     = *(float4*)&v[0];
        *(float4*)&C[(size_t)grow * DB + tx * 8 + 4] = *(float4*)&v[4];
    }
}

// ----------------------------------------------------------------------------
// Edge kernel v4: split-tf32 mma Wij + smem round-trip + COALESCED epilogue.
//   Phase 1: stage A' = [f_hi | f_hi | f_lo | 1 1 0 0]  (coalesced f loads)
//   Phase 2: mma -> acc regs  (D = f@Wf + b, exact to ~1e-7)
//   Phase 3: STS acc -> Wij smem [128 pairs][136]
//   Phase 4: warp-per-pair epilogue: LDS.128 Wij row, ssp*rcut,
//            coalesced LDG.128 h[j], coalesced red.v4 agg[i].
// ----------------------------------------------------------------------------
__global__ void __launch_bounds__(256, 2) edge_mma_kernel(
    const float* __restrict__ f, const float* __restrict__ rcut,
    const float* __restrict__ Wf, const float* __restrict__ bf)
{
    extern __shared__ float smem_dyn[];
    float* const Ws = smem_dyn;             // Wij [128][136]; A' in first 128*64
    float* const As = smem_dyn;             // alias
    float* const Bs = smem_dyn + W_ELEMS;   // B' [64][136]

    const int tid = threadIdx.x;
    const int wid = tid >> 5;        // 0..7
    const int lane = tid & 31;
    const int lq = lane >> 2;        // groupID 0..7
    const int la = lane & 3;         // threadID_in_group 0..3
    const int cb = wid * 16;         // mma output col base for this warp

    // ---- Stage B' (once per block) ----
    for (int e = tid; e < 64 * 128; e += 256) {
        int k = e >> 7;
        int n = e & 127;
        float val;
        if (k < 20) {
            val = tf32_rna(Wf[k * DB + n]);
        } else if (k < 40) {
            float w = Wf[(k - 20) * DB + n];
            val = tf32_rna(w - tf32_rna(w));
        } else if (k < 60) {
            val = tf32_rna(Wf[(k - 40) * DB + n]);
        } else if (k == 60) {
            val = tf32_rna(bf[n]);
        } else if (k == 61) {
            float b = bf[n];
            val = tf32_rna(b - tf32_rna(b));
        } else {
            val = 0.f;
        }
        Bs[k * 136 + n] = val;
    }

    for (int tile = blockIdx.x; tile < N_TILES; tile += EDGE_GRID) {
        __syncthreads();   // prev epilogue's Ws reads done before restaging

        // ---- Phase 1: stage A'. Coalesced walk of the contiguous f tile. ----
        {
            const float* ftile = f + (size_t)tile * TILE_P * NRBF;
            const int base = tile * TILE_P;
            const int rem = N_PAIRS - base;               // >0
            const int nelem = (rem >= TILE_P ? TILE_P : rem) * NRBF;
            for (int e = tid; e < TILE_P * NRBF; e += 256) {
                float x = (e < nelem) ? __ldg(&ftile[e]) : 0.f;
                int r = e / NRBF;
                int k = e - r * NRBF;
                float hi = tf32_rna(x);
                float lo = tf32_rna(x - hi);
                As[a_idx(r, k)]      = hi;
                As[a_idx(r, k + 20)] = hi;
                As[a_idx(r, k + 40)] = lo;
            }
            // constant cols 60..63 (clobbered each tile by phase 3)
            for (int e = tid; e < 512; e += 256) {
                int r = e >> 2;
                int c = 60 + (e & 3);
                As[a_idx(r, c)] = ((e & 3) < 2) ? 1.f : 0.f;
            }
        }
        __syncthreads();

        // ---- Phase 2: MMA (validated mapping from R9) ----
        float acc[8][2][4];
        #pragma unroll
        for (int mt = 0; mt < 8; mt++)
            #pragma unroll
            for (int nt = 0; nt < 2; nt++)
                #pragma unroll
                for (int q = 0; q < 4; q++) acc[mt][nt][q] = 0.f;

        #pragma unroll
        for (int kt = 0; kt < 8; kt++) {
            const int krow = kt * 8 + la;
            const uint32_t b00 = __float_as_uint(Bs[krow * 136 + cb + lq]);
            const uint32_t b01 = __float_as_uint(Bs[(krow + 4) * 136 + cb + lq]);
            const uint32_t b10 = __float_as_uint(Bs[krow * 136 + cb + 8 + lq]);
            const uint32_t b11 = __float_as_uint(Bs[(krow + 4) * 136 + cb + 8 + lq]);
            const int cx = (kt * 8 + la) ^ (lq << 2);
            #pragma unroll
            for (int mt = 0; mt < 8; mt++) {
                const int row = mt * 16 + lq;
                uint32_t a0 = __float_as_uint(As[row * 64 + cx]);
                uint32_t a1 = __float_as_uint(As[(row + 8) * 64 + cx]);
                uint32_t a2 = __float_as_uint(As[row * 64 + (cx ^ 4)]);
                uint32_t a3 = __float_as_uint(As[(row + 8) * 64 + (cx ^ 4)]);
                mma_tf32(acc[mt][0], a0, a1, a2, a3, b00, b01);
                mma_tf32(acc[mt][1], a0, a1, a2, a3, b10, b11);
            }
        }
        __syncthreads();   // all A' reads done before Ws overwrite

        // ---- Phase 3: STS acc -> Wij[pair][col] ----
        // D frag: rows mt*16+lq (c0,c1), mt*16+8+lq (c2,c3); cols cb+nt*8+2la,+1
        #pragma unroll
        for (int mt = 0; mt < 8; mt++)
            #pragma unroll
            for (int nt = 0; nt < 2; nt++) {
                int col = cb + nt * 8 + 2 * la;
                *(float2*)&Ws[(mt * 16 + lq) * 136 + col] =
                    make_float2(acc[mt][nt][0], acc[mt][nt][1]);
                *(float2*)&Ws[(mt * 16 + 8 + lq) * 136 + col] =
                    make_float2(acc[mt][nt][2], acc[mt][nt][3]);
            }
        __syncthreads();

        // ---- Phase 4: warp-per-pair coalesced epilogue ----
        {
            const int base = tile * TILE_P + wid * 16;
            #pragma unroll
            for (int q = 0; q < 16; q++) {
                const int p = base + q;
                if (p < N_PAIRS) {
                    int2 ij = g_pairs[p];              // uniform broadcast
                    float rc = __ldg(&rcut[p]);
                    float4 wv = *(const float4*)&Ws[(wid * 16 + q) * 136 + 4 * lane];
                    float4 hv = *(const float4*)&g_h[(size_t)ij.y * DB + 4 * lane];
                    float4 v;
                    v.x = hv.x * (ssp(wv.x) * rc);
                    v.y = hv.y * (ssp(wv.y) * rc);
                    v.z = hv.z * (ssp(wv.z) * rc);
                    v.w = hv.w * (ssp(wv.w) * rc);
                    red_add_v4(&g_agg[(size_t)ij.x * DB + 4 * lane], v);
                }
            }
        }
    }
}

// ----------------------------------------------------------------------------

extern "C" void kernel_launch(void* const* d_in, const int* in_sizes, int n_in,
                              void* d_out, int out_size)
{
    const float* x     = (const float*)d_in[0];
    const void*  pl    = d_in[1];
    const float* f_ij  = (const float*)d_in[2];
    const float* rcut  = (const float*)d_in[3];
    const float* W_in  = (const float*)d_in[4];
    const float* b_in  = (const float*)d_in[5];
    const float* W_f   = (const float*)d_in[6];
    const float* b_f   = (const float*)d_in[7];
    const float* W_out = (const float*)d_in[8];
    const float* b_out = (const float*)d_in[9];
    float*       out   = (float*)d_out;

    float* hbuf;  cudaGetSymbolAddress((void**)&hbuf, g_h);
    float* abuf;  cudaGetSymbolAddress((void**)&abuf, g_agg);

    // Opt-in to >48KB dynamic smem (idempotent, capture-safe host call).
    cudaFuncSetAttribute(edge_mma_kernel,
                         cudaFuncAttributeMaxDynamicSharedMemorySize, SMEM_EDGE);

    const int gemm_grid = (N_ATOMS + 127) / 128;  // 391

    // 0) pairlist convert (with in-kernel dtype sniff)
    convert_idx_kernel<<<(N_PAIRS + 255) / 256, 256>>>(pl);
    // 1) agg = 0
    zero_agg_kernel<<<(N_ATOMS * DB / 4 + 255) / 256, 256>>>();
    // 2) h = x @ W_in + b_in
    gemm128_kernel<false><<<gemm_grid, 256>>>(x, W_in, b_in, hbuf, N_ATOMS);
    // 3) edges: warp-MMA Wij + coalesced gather/modulate/scatter
    edge_mma_kernel<<<EDGE_GRID, 256, SMEM_EDGE>>>(f_ij, rcut, W_f, b_f);
    // 4) out = ssp(agg @ W_out + b_out)
    gemm128_kernel<true><<<gemm_grid, 256>>>(abuf, W_out, b_out, out, N_ATOMS);
}

// round 11
// speedup vs baseline: 1.2158x; 1.0039x over previous
#include <cuda_runtime.h>
#include <cstdint>

#define N_ATOMS 50000
#define N_PAIRS 600000
#define DB 128
#define NRBF 20

#define TILE_P 128
#define N_TILES ((N_PAIRS + TILE_P - 1) / TILE_P)   // 4688
#define EDGE_GRID 296

// Dynamic smem layout (floats):
//   [0 .. 128*136)          Wij tile, rows=pairs, stride 136  (69.6 KB)
//       (first 128*64 words double as the A'-staging region before MMA)
//   [128*136 .. +64*136)    B' tile, stride 136               (34.8 KB)
#define W_ELEMS (128 * 136)
#define B_ELEMS (64 * 136)
#define SMEM_EDGE ((W_ELEMS + B_ELEMS) * 4)   // 104448 B -> 2 blocks/SM

// Scratch (allocation-free rule: __device__ globals)
__device__ float g_h[(size_t)N_ATOMS * DB];    // 25.6 MB
__device__ float g_agg[(size_t)N_ATOMS * DB];  // 25.6 MB
__device__ int2  g_pairs[N_PAIRS];             // 4.8 MB

// Fast shifted-softplus: softplus(x) - ln2, overflow-safe, MUFU-based.
__device__ __forceinline__ float ssp(float x) {
    float t = __expf(-fabsf(x));
    return fmaxf(x, 0.f) + __logf(1.f + t) - 0.6931471805599453f;
}

__device__ __forceinline__ void red_add_v4(float* a, float4 v) {
    asm volatile("red.global.add.v4.f32 [%0], {%1,%2,%3,%4};"
                 :: "l"(a), "f"(v.x), "f"(v.y), "f"(v.z), "f"(v.w)
                 : "memory");
}

// tf32 round-to-nearest: destination of cvt.rna.tf32.f32 is a b32 register.
__device__ __forceinline__ float tf32_rna(float x) {
    uint32_t y;
    asm("cvt.rna.tf32.f32 %0, %1;" : "=r"(y) : "f"(x));
    return __uint_as_float(y);
}

// Warp-level tf32 MMA: D[16,8] += A[16,8] * B[8,8]  (fp32 accumulate)
__device__ __forceinline__ void mma_tf32(float* d,
                                         uint32_t a0, uint32_t a1,
                                         uint32_t a2, uint32_t a3,
                                         uint32_t b0, uint32_t b1) {
    asm volatile(
        "mma.sync.aligned.m16n8k8.row.col.f32.tf32.tf32.f32 "
        "{%0,%1,%2,%3}, {%4,%5,%6,%7}, {%8,%9}, {%0,%1,%2,%3};"
        : "+f"(d[0]), "+f"(d[1]), "+f"(d[2]), "+f"(d[3])
        : "r"(a0), "r"(a1), "r"(a2), "r"(a3), "r"(b0), "r"(b1));
}

// A'-staging index: row-major [128][64] with XOR swizzle -> conflict-free
// mma A-fragment loads. (Same mapping as R9, validated by rel_err 8e-7.)
__device__ __forceinline__ int a_idx(int r, int c) {
    return r * 64 + (c ^ ((r & 7) << 2));
}

// ----------------------------------------------------------------------------
// Pairlist convert to int2 with per-block dtype detection (int64 vs int32).
// ----------------------------------------------------------------------------
__global__ void convert_idx_kernel(const void* __restrict__ pl) {
    __shared__ unsigned int s_or;
    if (threadIdx.x == 0) s_or = 0u;
    __syncthreads();
    const unsigned int* pw = (const unsigned int*)pl;
    unsigned int v = 0u;
    for (int i = threadIdx.x; i < 1024; i += blockDim.x)
        v |= pw[2 * i + 1];
    atomicOr(&s_or, v);
    __syncthreads();
    const bool is64 = (s_or == 0u);

    int p = blockIdx.x * blockDim.x + threadIdx.x;
    if (p >= N_PAIRS) return;
    int i, j;
    if (is64) {
        const long long* q = (const long long*)pl;
        i = (int)q[p];
        j = (int)q[N_PAIRS + p];
    } else {
        const int* q = (const int*)pl;
        i = q[p];
        j = q[N_PAIRS + p];
    }
    g_pairs[p] = make_int2(i, j);
}

__global__ void zero_agg_kernel() {
    size_t idx = (size_t)blockIdx.x * blockDim.x + threadIdx.x;
    size_t n4 = (size_t)N_ATOMS * DB / 4;
    if (idx < n4)
        ((float4*)g_agg)[idx] = make_float4(0.f, 0.f, 0.f, 0.f);
}

// ----------------------------------------------------------------------------
// C[M,128] = A[M,128] @ W[128,128] + bias  (optional ssp epilogue) — fp32 SGEMM
// ----------------------------------------------------------------------------
template <bool DO_SSP>
__global__ __launch_bounds__(256) void gemm128_kernel(
    const float* __restrict__ A, const float* __restrict__ W,
    const float* __restrict__ bias, float* __restrict__ C, int M)
{
    __shared__ float As[16 * 132];
    __shared__ float Bs[16 * 128];

    const int tid = threadIdx.x;
    const int tx = tid & 15;
    const int ty = tid >> 4;
    const int m0 = blockIdx.x * 128;

    float acc[8][8];
    #pragma unroll
    for (int i = 0; i < 8; i++)
        #pragma unroll
        for (int j = 0; j < 8; j++) acc[i][j] = 0.f;

    for (int kt = 0; kt < 128; kt += 16) {
        #pragma unroll
        for (int i = 0; i < 2; i++) {
            int idx = tid * 2 + i;
            int row = idx >> 2;
            int c4  = idx & 3;
            float4 av = make_float4(0.f, 0.f, 0.f, 0.f);
            int grow = m0 + row;
            if (grow < M)
                av = *(const float4*)&A[(size_t)grow * DB + kt + c4 * 4];
            As[(c4 * 4 + 0) * 132 + row] = av.x;
            As[(c4 * 4 + 1) * 132 + row] = av.y;
            As[(c4 * 4 + 2) * 132 + row] = av.z;
            As[(c4 * 4 + 3) * 132 + row] = av.w;

            int k = idx >> 5;
            int c = idx & 31;
            *(float4*)&Bs[k * 128 + c * 4] =
                *(const float4*)&W[(size_t)(kt + k) * DB + c * 4];
        }
        __syncthreads();

        #pragma unroll
        for (int kk = 0; kk < 16; kk++) {
            float a[8], b[8];
            *(float4*)&a[0] = *(const float4*)&As[kk * 132 + ty * 8];
            *(float4*)&a[4] = *(const float4*)&As[kk * 132 + ty * 8 + 4];
            *(float4*)&b[0] = *(const float4*)&Bs[kk * 128 + tx * 8];
            *(float4*)&b[4] = *(const float4*)&Bs[kk * 128 + tx * 8 + 4];
            #pragma unroll
            for (int i = 0; i < 8; i++)
                #pragma unroll
                for (int j = 0; j < 8; j++)
                    acc[i][j] = fmaf(a[i], b[j], acc[i][j]);
        }
        __syncthreads();
    }

    float bb[8];
    *(float4*)&bb[0] = *(const float4*)&bias[tx * 8];
    *(float4*)&bb[4] = *(const float4*)&bias[tx * 8 + 4];

    #pragma unroll
    for (int i = 0; i < 8; i++) {
        int grow = m0 + ty * 8 + i;
        if (grow >= M) continue;
        float v[8];
        #pragma unroll
        for (int j = 0; j < 8; j++) {
            float c = acc[i][j] + bb[j];
            v[j] = DO_SSP ? ssp(c) : c;
        }
        *(float4*)&C[(size_t)grow * DB + tx * 8]     = *(float4*)&v[0];
        *(float4*)&C[(size_t)grow * DB + tx * 8 + 4] = *(float4*)&v[4];
    }
}

// ----------------------------------------------------------------------------
// Edge kernel v4: split-tf32 mma Wij + smem round-trip + COALESCED epilogue.
//   Phase 1: stage A' = [f_hi | f_hi | f_lo | 1 1 0 0]  (coalesced f loads)
//   Phase 2: mma -> acc regs  (D = f@Wf + b, exact to ~1e-7)
//   Phase 3: STS acc -> Wij smem [128 pairs][136]
//   Phase 4: warp-per-pair epilogue: LDS.128 Wij row, ssp*rcut,
//            coalesced LDG.128 h[j], coalesced red.v4 agg[i].
// ----------------------------------------------------------------------------
__global__ void __launch_bounds__(256, 2) edge_mma_kernel(
    const float* __restrict__ f, const float* __restrict__ rcut,
    const float* __restrict__ Wf, const float* __restrict__ bf)
{
    extern __shared__ float smem_dyn[];
    float* const Ws = smem_dyn;             // Wij [128][136]; A' in first 128*64
    float* const As = smem_dyn;             // alias
    float* const Bs = smem_dyn + W_ELEMS;   // B' [64][136]

    const int tid = threadIdx.x;
    const int wid = tid >> 5;        // 0..7
    const int lane = tid & 31;
    const int lq = lane >> 2;        // groupID 0..7
    const int la = lane & 3;         // threadID_in_group 0..3
    const int cb = wid * 16;         // mma output col base for this warp

    // ---- Stage B' (once per block) ----
    for (int e = tid; e < 64 * 128; e += 256) {
        int k = e >> 7;
        int n = e & 127;
        float val;
        if (k < 20) {
            val = tf32_rna(Wf[k * DB + n]);
        } else if (k < 40) {
            float w = Wf[(k - 20) * DB + n];
            val = tf32_rna(w - tf32_rna(w));
        } else if (k < 60) {
            val = tf32_rna(Wf[(k - 40) * DB + n]);
        } else if (k == 60) {
            val = tf32_rna(bf[n]);
        } else if (k == 61) {
            float b = bf[n];
            val = tf32_rna(b - tf32_rna(b));
        } else {
            val = 0.f;
        }
        Bs[k * 136 + n] = val;
    }

    for (int tile = blockIdx.x; tile < N_TILES; tile += EDGE_GRID) {
        __syncthreads();   // prev epilogue's Ws reads done before restaging

        // ---- Phase 1: stage A'. Coalesced walk of the contiguous f tile. ----
        {
            const float* ftile = f + (size_t)tile * TILE_P * NRBF;
            const int base = tile * TILE_P;
            const int rem = N_PAIRS - base;               // >0
            const int nelem = (rem >= TILE_P ? TILE_P : rem) * NRBF;
            for (int e = tid; e < TILE_P * NRBF; e += 256) {
                float x = (e < nelem) ? __ldg(&ftile[e]) : 0.f;
                int r = e / NRBF;
                int k = e - r * NRBF;
                float hi = tf32_rna(x);
                float lo = tf32_rna(x - hi);
                As[a_idx(r, k)]      = hi;
                As[a_idx(r, k + 20)] = hi;
                As[a_idx(r, k + 40)] = lo;
            }
            // constant cols 60..63 (clobbered each tile by phase 3)
            for (int e = tid; e < 512; e += 256) {
                int r = e >> 2;
                int c = 60 + (e & 3);
                As[a_idx(r, c)] = ((e & 3) < 2) ? 1.f : 0.f;
            }
        }
        __syncthreads();

        // ---- Phase 2: MMA (validated mapping from R9) ----
        float acc[8][2][4];
        #pragma unroll
        for (int mt = 0; mt < 8; mt++)
            #pragma unroll
            for (int nt = 0; nt < 2; nt++)
                #pragma unroll
                for (int q = 0; q < 4; q++) acc[mt][nt][q] = 0.f;

        #pragma unroll
        for (int kt = 0; kt < 8; kt++) {
            const int krow = kt * 8 + la;
            const uint32_t b00 = __float_as_uint(Bs[krow * 136 + cb + lq]);
            const uint32_t b01 = __float_as_uint(Bs[(krow + 4) * 136 + cb + lq]);
            const uint32_t b10 = __float_as_uint(Bs[krow * 136 + cb + 8 + lq]);
            const uint32_t b11 = __float_as_uint(Bs[(krow + 4) * 136 + cb + 8 + lq]);
            const int cx = (kt * 8 + la) ^ (lq << 2);
            #pragma unroll
            for (int mt = 0; mt < 8; mt++) {
                const int row = mt * 16 + lq;
                uint32_t a0 = __float_as_uint(As[row * 64 + cx]);
                uint32_t a1 = __float_as_uint(As[(row + 8) * 64 + cx]);
                uint32_t a2 = __float_as_uint(As[row * 64 + (cx ^ 4)]);
                uint32_t a3 = __float_as_uint(As[(row + 8) * 64 + (cx ^ 4)]);
                mma_tf32(acc[mt][0], a0, a1, a2, a3, b00, b01);
                mma_tf32(acc[mt][1], a0, a1, a2, a3, b10, b11);
            }
        }
        __syncthreads();   // all A' reads done before Ws overwrite

        // ---- Phase 3: STS acc -> Wij[pair][col] ----
        // D frag: rows mt*16+lq (c0,c1), mt*16+8+lq (c2,c3); cols cb+nt*8+2la,+1
        #pragma unroll
        for (int mt = 0; mt < 8; mt++)
            #pragma unroll
            for (int nt = 0; nt < 2; nt++) {
                int col = cb + nt * 8 + 2 * la;
                *(float2*)&Ws[(mt * 16 + lq) * 136 + col] =
                    make_float2(acc[mt][nt][0], acc[mt][nt][1]);
                *(float2*)&Ws[(mt * 16 + 8 + lq) * 136 + col] =
                    make_float2(acc[mt][nt][2], acc[mt][nt][3]);
            }
        __syncthreads();

        // ---- Phase 4: warp-per-pair coalesced epilogue ----
        {
            const int base = tile * TILE_P + wid * 16;
            #pragma unroll
            for (int q = 0; q < 16; q++) {
                const int p = base + q;
                if (p < N_PAIRS) {
                    int2 ij = g_pairs[p];              // uniform broadcast
                    float rc = __ldg(&rcut[p]);
                    float4 wv = *(const float4*)&Ws[(wid * 16 + q) * 136 + 4 * lane];
                    float4 hv = *(const float4*)&g_h[(size_t)ij.y * DB + 4 * lane];
                    float4 v;
                    v.x = hv.x * (ssp(wv.x) * rc);
                    v.y = hv.y * (ssp(wv.y) * rc);
                    v.z = hv.z * (ssp(wv.z) * rc);
                    v.w = hv.w * (ssp(wv.w) * rc);
                    red_add_v4(&g_agg[(size_t)ij.x * DB + 4 * lane], v);
                }
            }
        }
    }
}

// ----------------------------------------------------------------------------

extern "C" void kernel_launch(void* const* d_in, const int* in_sizes, int n_in,
                              void* d_out, int out_size)
{
    const float* x     = (const float*)d_in[0];
    const void*  pl    = d_in[1];
    const float* f_ij  = (const float*)d_in[2];
    const float* rcut  = (const float*)d_in[3];
    const float* W_in  = (const float*)d_in[4];
    const float* b_in  = (const float*)d_in[5];
    const float* W_f   = (const float*)d_in[6];
    const float* b_f   = (const float*)d_in[7];
    const float* W_out = (const float*)d_in[8];
    const float* b_out = (const float*)d_in[9];
    float*       out   = (float*)d_out;

    float* hbuf;  cudaGetSymbolAddress((void**)&hbuf, g_h);
    float* abuf;  cudaGetSymbolAddress((void**)&abuf, g_agg);

    // Opt-in to >48KB dynamic smem (idempotent, capture-safe host call).
    cudaFuncSetAttribute(edge_mma_kernel,
                         cudaFuncAttributeMaxDynamicSharedMemorySize, SMEM_EDGE);

    const int gemm_grid = (N_ATOMS + 127) / 128;  // 391

    // 0) pairlist convert (with in-kernel dtype sniff)
    convert_idx_kernel<<<(N_PAIRS + 255) / 256, 256>>>(pl);
    // 1) agg = 0
    zero_agg_kernel<<<(N_ATOMS * DB / 4 + 255) / 256, 256>>>();
    // 2) h = x @ W_in + b_in
    gemm128_kernel<false><<<gemm_grid, 256>>>(x, W_in, b_in, hbuf, N_ATOMS);
    // 3) edges: warp-MMA Wij + coalesced gather/modulate/scatter
    edge_mma_kernel<<<EDGE_GRID, 256, SMEM_EDGE>>>(f_ij, rcut, W_f, b_f);
    // 4) out = ssp(agg @ W_out + b_out)
    gemm128_kernel<true><<<gemm_grid, 256>>>(abuf, W_out, b_out, out, N_ATOMS);
}